// round 4
// baseline (speedup 1.0000x reference)
#include <cuda_runtime.h>
#include <cuda_bf16.h>
#include <cstdint>

#define BB 8
#define NN 50000
#define CC 8
#define CAP 2048
#define KP 1024
#define MAXD 100
#define SCORE_THR 0.99f
#define NSPLIT 8

typedef unsigned long long u64;
typedef unsigned int u32;

// ---------------- device scratch (no allocations allowed) -------------------
__device__ int   g_cnt[BB * CC];          // zero-initialized at load; re-zeroed by k3_final
__device__ float g_cscore[BB * CC * CAP];
__device__ int   g_cidx[BB * CC * CAP];

__device__ int   g_M[BB * CC];
__device__ float g_sx1[BB * CC * KP];
__device__ float g_sy1[BB * CC * KP];
__device__ float g_sx2[BB * CC * KP];
__device__ float g_sy2[BB * CC * KP];
__device__ float g_sar[BB * CC * KP];
__device__ u64   g_skey[BB * CC * KP];
__device__ int   g_sidx[BB * CC * KP];

__device__ u32   g_mask[BB * CC * KP * 32];   // 8 MB row-bitmask scratch

// ---------------------------------------------------------------------------
// Candidate compaction. b = blockIdx.y -> warp-uniform batch.
__global__ void __launch_bounds__(256) k1_cand(const float* __restrict__ cls) {
    int b = blockIdx.y;
    int n = blockIdx.x * 256 + threadIdx.x;
    bool valid = n < NN;
    float v[8];
    if (valid) {
        const float4* p = reinterpret_cast<const float4*>(cls + ((size_t)b * NN + n) * CC);
        float4 v0 = p[0], v1 = p[1];
        v[0]=v0.x; v[1]=v0.y; v[2]=v0.z; v[3]=v0.w;
        v[4]=v1.x; v[5]=v1.y; v[6]=v1.z; v[7]=v1.w;
    } else {
#pragma unroll
        for (int c = 0; c < 8; c++) v[c] = 0.0f;
    }
    int lane = threadIdx.x & 31;
#pragma unroll
    for (int c = 0; c < 8; c++) {
        bool p = v[c] > SCORE_THR;
        u32 m = __ballot_sync(0xffffffffu, p);
        if (m) {
            int leader = __ffs(m) - 1;
            int base = 0;
            if (lane == leader) base = atomicAdd(&g_cnt[b * CC + c], __popc(m));
            base = __shfl_sync(0xffffffffu, base, leader);
            if (p) {
                int off = base + __popc(m & ((1u << lane) - 1u));
                if (off < CAP) {
                    g_cscore[(b * CC + c) * CAP + off] = v[c];
                    g_cidx[(b * CC + c) * CAP + off]   = n;
                }
            }
        }
    }
}

// ---------------------------------------------------------------------------
__device__ __forceinline__ void bitonic_desc(u64* s, int n, int tid, int nthreads) {
    for (int k = 2; k <= n; k <<= 1) {
        for (int j = k >> 1; j > 0; j >>= 1) {
            for (int i = tid; i < n; i += nthreads) {
                int ixj = i ^ j;
                if (ixj > i) {
                    u64 a = s[i], c = s[ixj];
                    bool up = ((i & k) == 0);
                    if (up ? (a < c) : (a > c)) { s[i] = c; s[ixj] = a; }
                }
            }
            __syncthreads();
        }
    }
}

// ---------------------------------------------------------------------------
// Sort candidates (size = next pow2 of cnt) + gather sorted box coords.
__global__ void __launch_bounds__(512) k2a_sort(const float* __restrict__ boxes) {
    __shared__ u64 keys[CAP];
    int bc = blockIdx.x;
    int b  = bc >> 3;
    int tid = threadIdx.x;

    int cnt = g_cnt[bc];
    if (cnt > CAP) cnt = CAP;
    int P = 64;
    while (P < cnt) P <<= 1;

    for (int t = tid; t < P; t += 512) {
        u64 k = 0ull;
        if (t < cnt) {
            u32 sb = __float_as_uint(g_cscore[bc * CAP + t]);
            u32 iv = ~(u32)g_cidx[bc * CAP + t];
            k = ((u64)sb << 32) | (u64)iv;
        }
        keys[t] = k;
    }
    __syncthreads();
    bitonic_desc(keys, P, tid, 512);

    int M = cnt < KP ? cnt : KP;
    if (tid == 0) g_M[bc] = M;

    for (int t = tid; t < M; t += 512) {
        u64 kk = keys[t];
        int idx = (int)(~(u32)kk);
        float4 bp = reinterpret_cast<const float4*>(boxes)[(size_t)(b * NN + idx)];
        int o = bc * KP + t;
        g_sx1[o] = bp.x; g_sy1[o] = bp.y; g_sx2[o] = bp.z; g_sy2[o] = bp.w;
        g_sar[o] = __fmul_rn(__fsub_rn(bp.z, bp.x), __fsub_rn(bp.w, bp.y));
        g_skey[o] = kk;
        g_sidx[o] = idx;
    }
}

// ---------------------------------------------------------------------------
// Triangular IoU mask build. Work item = (iw, g): i-word iw vs j-word chunk
// [4g, 4g+4). Only words < nW are produced (scan reads no further). Each lane
// holds 4 j-boxes in registers; i-box broadcast from smem per iteration.
__global__ void __launch_bounds__(256) k2b_mask() {
    __shared__ float sx1[KP], sy1[KP], sx2[KP], sy2[KP], sar[KP];
    int bc = blockIdx.x >> 3;        // NSPLIT = 8 blocks per bc
    int s  = blockIdx.x & 7;
    int M  = g_M[bc];
    int nW = (M + 31) >> 5;
    int nG = (nW + 3) >> 2;

    for (int t = threadIdx.x; t < M; t += 256) {
        int o = bc * KP + t;
        sx1[t] = g_sx1[o]; sy1[t] = g_sy1[o];
        sx2[t] = g_sx2[o]; sy2[t] = g_sy2[o];
        sar[t] = g_sar[o];
    }
    __syncthreads();

    int w = threadIdx.x >> 5, lane = threadIdx.x & 31;
    int slot = s * 8 + w;            // 0..63 warps per bc
    int e = 0;
    for (int iw = 0; iw < nW; iw++) {
        for (int g = iw >> 2; g < nG; g++, e++) {
            if ((e & 63) != slot) continue;

            float jx1[4], jy1[4], jx2[4], jy2[4], ja[4];
            int jbase = (g << 7) + lane;
#pragma unroll
            for (int k = 0; k < 4; k++) {
                int j = jbase + (k << 5);          // < KP always (g <= 7)
                jx1[k] = sx1[j]; jy1[k] = sy1[j];
                jx2[k] = sx2[j]; jy2[k] = sy2[j];
                ja[k]  = sar[j];
            }
            int i0 = iw << 5;
            int dmax = M - i0; if (dmax > 32) dmax = 32;
            for (int d = 0; d < dmax; d++) {
                int i = i0 + d;
                float ix1 = sx1[i], iy1 = sy1[i], ix2 = sx2[i], iy2 = sy2[i], ia = sar[i];
                u32 mm[4];
#pragma unroll
                for (int k = 0; k < 4; k++) {
                    int j = jbase + (k << 5);
                    float ww = fmaxf(__fsub_rn(fminf(ix2, jx2[k]), fmaxf(ix1, jx1[k])), 0.0f);
                    float hh = fmaxf(__fsub_rn(fminf(iy2, jy2[k]), fmaxf(iy1, jy1[k])), 0.0f);
                    float inter = __fmul_rn(ww, hh);
                    float den   = __fsub_rn(__fadd_rn(ia, ja[k]), inter);
                    bool p = (j > i) && (j < M) && (__fdiv_rn(inter, den) > 0.5f);
                    mm[k] = __ballot_sync(0xffffffffu, p);
                }
                if (lane == 0) {
                    reinterpret_cast<uint4*>(g_mask)[(size_t)(bc * KP + i) * 8 + g] =
                        make_uint4(mm[0], mm[1], mm[2], mm[3]);
                }
            }
        }
    }
}

// ---------------------------------------------------------------------------
// Fused: greedy NMS scan (8 warps, one per class) + compaction to smem +
// final per-batch top-100 sort + output assembly. Also re-zeros g_cnt.
__global__ void __launch_bounds__(1024) k3_final(const float* __restrict__ boxes,
                                                 const float* __restrict__ rot,
                                                 const float* __restrict__ trans,
                                                 float* __restrict__ out) {
    __shared__ u64 keys[1024];
    int b = blockIdx.x, tid = threadIdx.x;
    keys[tid] = 0ull;
    if (tid < 8) g_cnt[b * 8 + tid] = 0;   // reset for next graph replay
    __syncthreads();

    int warp = tid >> 5, lane = tid & 31;
    if (warp < 8) {
        int c = warp, bc = b * 8 + c;
        int M  = g_M[bc];
        int nW = (M + 31) >> 5;
        const u32* mrow = g_mask + ((size_t)(bc * KP) << 5);
        bool lw = lane < nW;

        u32 RW[16], DG[16];
#pragma unroll
        for (int d = 0; d < 16; d++) {
            RW[d] = (d < M && lw) ? mrow[(d << 5) + lane]     : 0u;
            DG[d] = (d < M)       ? mrow[(d << 5) + (d >> 5)] : 0u;
        }

        u32 remv = 0u, keepreg = 0u;
        for (int g1 = 0; g1 < nW; g1++) {
            u32 cur = __shfl_sync(0xffffffffu, remv, g1);
            u32 valid = (lane >= g1) ? 0xffffffffu : 0u;
            u32 kw = 0u;
#pragma unroll
            for (int sub = 0; sub < 2; sub++) {
#pragma unroll
                for (int d = 0; d < 16; d++) {
                    int i = (g1 << 5) + (sub << 4) + d;
                    u32 rw = RW[d], dg = DG[d];
                    int ip = i + 16;
                    RW[d] = (ip < M && lw) ? mrow[(ip << 5) + lane]      : 0u;
                    DG[d] = (ip < M)       ? mrow[(ip << 5) + (ip >> 5)] : 0u;
                    if (i < M && !((cur >> (i & 31)) & 1u)) {
                        kw   |= 1u << (i & 31);
                        cur  |= dg;
                        remv |= rw & valid;
                    }
                }
            }
            if (lane == g1) keepreg = kw;
        }

        // compact kept entries (order preserved -> still score-sorted)
        int cntl = __popc(keepreg);
        int pre = cntl;
#pragma unroll
        for (int o = 1; o < 32; o <<= 1) {
            int vv = __shfl_up_sync(0xffffffffu, pre, o);
            if (lane >= o) pre += vv;
        }
        int off = pre - cntl;
        u32 wb = keepreg;
        while (wb && off < 128) {
            int b2 = __ffs(wb) - 1;
            wb &= wb - 1;
            int i = (lane << 5) + b2;
            u64 sk = g_skey[bc * KP + i];
            keys[c * 128 + off] = (sk & 0xffffffff00000000ull) | (u64)(~(u32)(c * KP + i));
            off++;
        }
    }
    __syncthreads();
    bitonic_desc(keys, 1024, tid, 1024);

    if (tid < MAXD) {
        float* ob   = out;
        float* os   = out + 3200;
        float* ol   = out + 4000;
        float* orot = out + 4800;
        float* otr  = out + 7200;
        int base = b * MAXD + tid;

        u64 kk = keys[tid];
        if (kk != 0ull) {
            u32 t = ~(u32)kk;
            int c2   = (int)(t >> 10);
            int slot = (int)(t & 1023u);
            int idx  = g_sidx[(b * 8 + c2) * KP + slot];
            float s  = __uint_as_float((u32)(kk >> 32));
            size_t g = (size_t)(b * NN + idx);
            float4 bp = reinterpret_cast<const float4*>(boxes)[g];
            ob[base * 4 + 0] = bp.x;
            ob[base * 4 + 1] = bp.y;
            ob[base * 4 + 2] = bp.z;
            ob[base * 4 + 3] = bp.w;
            os[base] = s;
            ol[base] = (float)c2;
            const float* rp = rot + g * 3;
            orot[base * 3 + 0] = rp[0];
            orot[base * 3 + 1] = rp[1];
            orot[base * 3 + 2] = rp[2];
            const float* tp = trans + g * 3;
            otr[base * 3 + 0] = tp[0];
            otr[base * 3 + 1] = tp[1];
            otr[base * 3 + 2] = tp[2];
        } else {
            ob[base * 4 + 0] = -1.0f;
            ob[base * 4 + 1] = -1.0f;
            ob[base * 4 + 2] = -1.0f;
            ob[base * 4 + 3] = -1.0f;
            os[base] = -1.0f;
            ol[base] = -1.0f;
            orot[base * 3 + 0] = -1.0f;
            orot[base * 3 + 1] = -1.0f;
            orot[base * 3 + 2] = -1.0f;
            otr[base * 3 + 0] = -1.0f;
            otr[base * 3 + 1] = -1.0f;
            otr[base * 3 + 2] = -1.0f;
        }
    }
}

// ---------------------------------------------------------------------------
extern "C" void kernel_launch(void* const* d_in, const int* in_sizes, int n_in,
                              void* d_out, int out_size) {
    const float* boxes = (const float*)d_in[0];
    const float* cls   = (const float*)d_in[1];
    const float* rot   = (const float*)d_in[2];
    const float* trans = (const float*)d_in[3];
    float* out = (float*)d_out;

    k1_cand<<<dim3((NN + 255) / 256, BB), 256>>>(cls);
    k2a_sort<<<BB * CC, 512>>>(boxes);
    k2b_mask<<<BB * CC * NSPLIT, 256>>>();
    k3_final<<<BB, 1024>>>(boxes, rot, trans, out);
}

// round 7
// speedup vs baseline: 1.0049x; 1.0049x over previous
#include <cuda_runtime.h>
#include <cuda_bf16.h>
#include <cstdint>

#define BB 8
#define NN 50000
#define CC 8
#define CAP 2048
#define KP 1024
#define MAXD 100
#define SCORE_THR 0.99f

typedef unsigned long long u64;
typedef unsigned int u32;

// ---------------- device scratch (no allocations allowed) -------------------
__device__ int   g_cnt[BB * CC];          // zero at load; re-zeroed by k3_rank
__device__ float g_cscore[BB * CC * CAP];
__device__ int   g_cidx[BB * CC * CAP];

__device__ int   g_M[BB * CC];
__device__ float g_sx1[BB * CC * KP];
__device__ float g_sy1[BB * CC * KP];
__device__ float g_sx2[BB * CC * KP];
__device__ float g_sy2[BB * CC * KP];
__device__ float g_sar[BB * CC * KP];
__device__ u64   g_skey[BB * CC * KP];
__device__ int   g_sidx[BB * CC * KP];

__device__ int   g_kcnt[BB * CC];
__device__ u64   g_ckey[BB * CC * 128];   // top-128 kept keys per class, sorted

// ---------------------------------------------------------------------------
// Candidate compaction. b = blockIdx.y -> warp-uniform batch.
__global__ void __launch_bounds__(256) k1_cand(const float* __restrict__ cls) {
    int b = blockIdx.y;
    int n = blockIdx.x * 256 + threadIdx.x;
    bool valid = n < NN;
    float v[8];
    if (valid) {
        const float4* p = reinterpret_cast<const float4*>(cls + ((size_t)b * NN + n) * CC);
        float4 v0 = p[0], v1 = p[1];
        v[0]=v0.x; v[1]=v0.y; v[2]=v0.z; v[3]=v0.w;
        v[4]=v1.x; v[5]=v1.y; v[6]=v1.z; v[7]=v1.w;
    } else {
#pragma unroll
        for (int c = 0; c < 8; c++) v[c] = 0.0f;
    }
    int lane = threadIdx.x & 31;
#pragma unroll
    for (int c = 0; c < 8; c++) {
        bool p = v[c] > SCORE_THR;
        u32 m = __ballot_sync(0xffffffffu, p);
        if (m) {
            int leader = __ffs(m) - 1;
            int base = 0;
            if (lane == leader) base = atomicAdd(&g_cnt[b * CC + c], __popc(m));
            base = __shfl_sync(0xffffffffu, base, leader);
            if (p) {
                int off = base + __popc(m & ((1u << lane) - 1u));
                if (off < CAP) {
                    g_cscore[(b * CC + c) * CAP + off] = v[c];
                    g_cidx[(b * CC + c) * CAP + off]   = n;
                }
            }
        }
    }
}

// ---------------------------------------------------------------------------
__device__ __forceinline__ void bitonic_desc(u64* s, int n, int tid, int nthreads) {
    for (int k = 2; k <= n; k <<= 1) {
        for (int j = k >> 1; j > 0; j >>= 1) {
            for (int i = tid; i < n; i += nthreads) {
                int ixj = i ^ j;
                if (ixj > i) {
                    u64 a = s[i], c = s[ixj];
                    bool up = ((i & k) == 0);
                    if (up ? (a < c) : (a > c)) { s[i] = c; s[ixj] = a; }
                }
            }
            __syncthreads();
        }
    }
}

// ---------------------------------------------------------------------------
// Sort candidates (size = next pow2 of cnt) + gather sorted box coords.
__global__ void __launch_bounds__(512) k2a_sort(const float* __restrict__ boxes) {
    __shared__ u64 keys[CAP];
    int bc = blockIdx.x;
    int b  = bc >> 3;
    int tid = threadIdx.x;

    int cnt = g_cnt[bc];
    if (cnt > CAP) cnt = CAP;
    int P = 64;
    while (P < cnt) P <<= 1;

    for (int t = tid; t < P; t += 512) {
        u64 k = 0ull;
        if (t < cnt) {
            u32 sb = __float_as_uint(g_cscore[bc * CAP + t]);
            u32 iv = ~(u32)g_cidx[bc * CAP + t];
            k = ((u64)sb << 32) | (u64)iv;
        }
        keys[t] = k;
    }
    __syncthreads();
    bitonic_desc(keys, P, tid, 512);

    int M = cnt < KP ? cnt : KP;
    if (tid == 0) g_M[bc] = M;

    for (int t = tid; t < M; t += 512) {
        u64 kk = keys[t];
        int idx = (int)(~(u32)kk);
        float4 bp = reinterpret_cast<const float4*>(boxes)[(size_t)(b * NN + idx)];
        int o = bc * KP + t;
        g_sx1[o] = bp.x; g_sy1[o] = bp.y; g_sx2[o] = bp.z; g_sy2[o] = bp.w;
        g_sar[o] = __fmul_rn(__fsub_rn(bp.z, bp.x), __fsub_rn(bp.w, bp.y));
        g_skey[o] = kk;
        g_sidx[o] = idx;
    }
}

// ---------------------------------------------------------------------------
// Fused mask build + greedy scan, one block per (b,c), mask in SMEM.
// Dyn smem: mask[1024][32] u32 (128 KB) | boxes 5*1024 floats (20 KB)
#define K2BC_SMEM (131072 + 20480)

__global__ void __launch_bounds__(1024, 1) k2bc(const int dummy) {
    extern __shared__ unsigned char smem[];
    u32*   sm   = reinterpret_cast<u32*>(smem);            // mask, row stride 32
    float* sx1  = reinterpret_cast<float*>(smem + 131072);
    float* sy1  = sx1 + KP;
    float* sx2  = sy1 + KP;
    float* sy2  = sx2 + KP;
    float* sar  = sy2 + KP;

    int bc  = blockIdx.x;
    int c   = bc & 7;
    int tid = threadIdx.x;
    int M   = g_M[bc];
    int nW  = (M + 31) >> 5;
    int nG  = (nW + 3) >> 2;

    // zero mask + load boxes
    {
        uint4 z = make_uint4(0,0,0,0);
        uint4* m4 = reinterpret_cast<uint4*>(sm);
        for (int t = tid; t < 8192; t += 1024) m4[t] = z;
        for (int t = tid; t < M; t += 1024) {
            int o = bc * KP + t;
            sx1[t] = g_sx1[o]; sy1[t] = g_sy1[o];
            sx2[t] = g_sx2[o]; sy2[t] = g_sy2[o];
            sar[t] = g_sar[o];
        }
    }
    __syncthreads();

    int w = tid >> 5, lane = tid & 31;
    // mask build: item = (iw, g), round-robin over 32 warps
    int e = 0;
    for (int iw = 0; iw < nW; iw++) {
        for (int g = iw >> 2; g < nG; g++, e++) {
            if ((e & 31) != w) continue;
            float jx1[4], jy1[4], jx2[4], jy2[4], ja[4];
            int jbase = (g << 7) + lane;
#pragma unroll
            for (int k = 0; k < 4; k++) {
                int j = jbase + (k << 5);
                jx1[k] = sx1[j]; jy1[k] = sy1[j];
                jx2[k] = sx2[j]; jy2[k] = sy2[j];
                ja[k]  = sar[j];
            }
            int i0 = iw << 5;
            int dmax = M - i0; if (dmax > 32) dmax = 32;
            for (int d = 0; d < dmax; d++) {
                int i = i0 + d;
                float ix1 = sx1[i], iy1 = sy1[i], ix2 = sx2[i], iy2 = sy2[i], ia = sar[i];
                u32 mm[4];
#pragma unroll
                for (int k = 0; k < 4; k++) {
                    int j = jbase + (k << 5);
                    float ww = fmaxf(__fsub_rn(fminf(ix2, jx2[k]), fmaxf(ix1, jx1[k])), 0.0f);
                    float hh = fmaxf(__fsub_rn(fminf(iy2, jy2[k]), fmaxf(iy1, jy1[k])), 0.0f);
                    float inter = __fmul_rn(ww, hh);
                    float den   = __fsub_rn(__fadd_rn(ia, ja[k]), inter);
                    bool p = (j > i) && (j < M) && (__fdiv_rn(inter, den) > 0.5f);
                    mm[k] = __ballot_sync(0xffffffffu, p);
                }
                if (lane == 0)
                    reinterpret_cast<uint4*>(sm)[(i << 3) + g] = make_uint4(mm[0], mm[1], mm[2], mm[3]);
            }
        }
    }
    __syncthreads();

    // serial greedy scan by warp 0, mask words from SMEM
    if (w == 0) {
        bool lw = lane < nW;
        u32 RW[16], DG[16];
#pragma unroll
        for (int d = 0; d < 16; d++) {
            RW[d] = (d < M && lw) ? sm[(d << 5) + lane]     : 0u;
            DG[d] = (d < M)       ? sm[(d << 5) + (d >> 5)] : 0u;
        }
        u32 remv = 0u, keepreg = 0u;
        for (int g1 = 0; g1 < nW; g1++) {
            u32 cur = __shfl_sync(0xffffffffu, remv, g1);
            u32 valid = (lane >= g1) ? 0xffffffffu : 0u;
            u32 kw = 0u;
#pragma unroll
            for (int sub = 0; sub < 2; sub++) {
#pragma unroll
                for (int d = 0; d < 16; d++) {
                    int i = (g1 << 5) + (sub << 4) + d;
                    u32 rw = RW[d], dg = DG[d];
                    int ip = i + 16;
                    RW[d] = (ip < M && lw) ? sm[(ip << 5) + lane]      : 0u;
                    DG[d] = (ip < M)       ? sm[(ip << 5) + (ip >> 5)] : 0u;
                    if (i < M && !((cur >> (i & 31)) & 1u)) {
                        kw   |= 1u << (i & 31);
                        cur  |= dg;
                        remv |= rw & valid;
                    }
                }
            }
            if (lane == g1) keepreg = kw;
        }

        // compact kept entries (order preserved -> still score-sorted), cap 128
        int cntl = __popc(keepreg);
        int pre = cntl;
#pragma unroll
        for (int o = 1; o < 32; o <<= 1) {
            int vv = __shfl_up_sync(0xffffffffu, pre, o);
            if (lane >= o) pre += vv;
        }
        int off = pre - cntl;
        int total = __shfl_sync(0xffffffffu, pre, 31);
        if (lane == 0) g_kcnt[bc] = total < 128 ? total : 128;
        u32 wb = keepreg;
        while (wb && off < 128) {
            int b2 = __ffs(wb) - 1;
            wb &= wb - 1;
            int i = (lane << 5) + b2;
            u64 sk = g_skey[bc * KP + i];
            g_ckey[bc * 128 + off] = (sk & 0xffffffff00000000ull) | (u64)(~(u32)(c * KP + i));
            off++;
        }
    }
}

// ---------------------------------------------------------------------------
// Final top-100 by parallel rank-selection over 8 sorted lists of <=128.
__global__ void __launch_bounds__(1024) k3_rank(const float* __restrict__ boxes,
                                                const float* __restrict__ rot,
                                                const float* __restrict__ trans,
                                                float* __restrict__ out) {
    __shared__ u64 lists[8][128];
    __shared__ int written[MAXD];
    int b = blockIdx.x, tid = threadIdx.x;
    int c = tid >> 7, k = tid & 127;
    int bc = b * 8 + c;

    if (tid < 8)    g_cnt[b * 8 + tid] = 0;   // reset for next graph replay
    if (tid < MAXD) written[tid] = 0;

    u64 key = 0ull;
    if (k < g_kcnt[bc]) key = g_ckey[bc * 128 + k];
    lists[c][k] = key;
    __syncthreads();

    float* ob   = out;
    float* os   = out + 3200;
    float* ol   = out + 4000;
    float* orot = out + 4800;
    float* otr  = out + 7200;

    if (key != 0ull) {
        int rank = 0;
#pragma unroll
        for (int c2 = 0; c2 < 8; c2++) {
            const u64* L = lists[c2];
            // exact lower bound: count of entries strictly greater than key
            int lo = 0, hi = 128;
            while (lo < hi) {
                int mid = (lo + hi) >> 1;
                if (L[mid] > key) lo = mid + 1; else hi = mid;
            }
            rank += lo;
        }
        if (rank < MAXD) {
            written[rank] = 1;
            int base = b * MAXD + rank;
            u32 t = ~(u32)key;
            int c3   = (int)(t >> 10);
            int slot = (int)(t & 1023u);
            int idx  = g_sidx[(b * 8 + c3) * KP + slot];
            float s  = __uint_as_float((u32)(key >> 32));
            size_t g = (size_t)(b * NN + idx);
            float4 bp = reinterpret_cast<const float4*>(boxes)[g];
            ob[base * 4 + 0] = bp.x;
            ob[base * 4 + 1] = bp.y;
            ob[base * 4 + 2] = bp.z;
            ob[base * 4 + 3] = bp.w;
            os[base] = s;
            ol[base] = (float)c3;
            const float* rp = rot + g * 3;
            orot[base * 3 + 0] = rp[0];
            orot[base * 3 + 1] = rp[1];
            orot[base * 3 + 2] = rp[2];
            const float* tp = trans + g * 3;
            otr[base * 3 + 0] = tp[0];
            otr[base * 3 + 1] = tp[1];
            otr[base * 3 + 2] = tp[2];
        }
    }
    __syncthreads();
    if (tid < MAXD && !written[tid]) {
        int base = b * MAXD + tid;
        ob[base * 4 + 0] = -1.0f;
        ob[base * 4 + 1] = -1.0f;
        ob[base * 4 + 2] = -1.0f;
        ob[base * 4 + 3] = -1.0f;
        os[base] = -1.0f;
        ol[base] = -1.0f;
        orot[base * 3 + 0] = -1.0f;
        orot[base * 3 + 1] = -1.0f;
        orot[base * 3 + 2] = -1.0f;
        otr[base * 3 + 0] = -1.0f;
        otr[base * 3 + 1] = -1.0f;
        otr[base * 3 + 2] = -1.0f;
    }
}

// ---------------------------------------------------------------------------
extern "C" void kernel_launch(void* const* d_in, const int* in_sizes, int n_in,
                              void* d_out, int out_size) {
    const float* boxes = (const float*)d_in[0];
    const float* cls   = (const float*)d_in[1];
    const float* rot   = (const float*)d_in[2];
    const float* trans = (const float*)d_in[3];
    float* out = (float*)d_out;

    cudaFuncSetAttribute(k2bc, cudaFuncAttributeMaxDynamicSharedMemorySize, K2BC_SMEM);

    k1_cand<<<dim3((NN + 255) / 256, BB), 256>>>(cls);
    k2a_sort<<<BB * CC, 512>>>(boxes);
    k2bc<<<BB * CC, 1024, K2BC_SMEM>>>(0);
    k3_rank<<<BB, 1024>>>(boxes, rot, trans, out);
}

// round 8
// speedup vs baseline: 1.0795x; 1.0743x over previous
#include <cuda_runtime.h>
#include <cuda_bf16.h>
#include <cstdint>

#define BB 8
#define NN 50000
#define CC 8
#define CAP 2048
#define KP 1024
#define MAXD 100
#define SCORE_THR 0.99f

typedef unsigned long long u64;
typedef unsigned int u32;

// ---------------- device scratch (no allocations allowed) -------------------
__device__ int   g_cnt[BB * CC];          // zero at load; re-zeroed by k3_rank
__device__ float g_cscore[BB * CC * CAP];
__device__ int   g_cidx[BB * CC * CAP];

__device__ int   g_kcnt[BB * CC];
__device__ u64   g_ckey[BB * CC * 128];   // top-128 kept keys per class (sorted)
__device__ int   g_cidxsel[BB * CC * 128];// matching original point index

// ---------------------------------------------------------------------------
// Candidate compaction. b = blockIdx.y -> warp-uniform batch.
__global__ void __launch_bounds__(256) k1_cand(const float* __restrict__ cls) {
    int b = blockIdx.y;
    int n = blockIdx.x * 256 + threadIdx.x;
    bool valid = n < NN;
    float v[8];
    if (valid) {
        const float4* p = reinterpret_cast<const float4*>(cls + ((size_t)b * NN + n) * CC);
        float4 v0 = p[0], v1 = p[1];
        v[0]=v0.x; v[1]=v0.y; v[2]=v0.z; v[3]=v0.w;
        v[4]=v1.x; v[5]=v1.y; v[6]=v1.z; v[7]=v1.w;
    } else {
#pragma unroll
        for (int c = 0; c < 8; c++) v[c] = 0.0f;
    }
    int lane = threadIdx.x & 31;
#pragma unroll
    for (int c = 0; c < 8; c++) {
        bool p = v[c] > SCORE_THR;
        u32 m = __ballot_sync(0xffffffffu, p);
        if (m) {
            int leader = __ffs(m) - 1;
            int base = 0;
            if (lane == leader) base = atomicAdd(&g_cnt[b * CC + c], __popc(m));
            base = __shfl_sync(0xffffffffu, base, leader);
            if (p) {
                int off = base + __popc(m & ((1u << lane) - 1u));
                if (off < CAP) {
                    g_cscore[(b * CC + c) * CAP + off] = v[c];
                    g_cidx[(b * CC + c) * CAP + off]   = n;
                }
            }
        }
    }
}

// ---------------------------------------------------------------------------
__device__ __forceinline__ void bitonic_desc(u64* s, int n, int tid, int nthreads) {
    for (int k = 2; k <= n; k <<= 1) {
        for (int j = k >> 1; j > 0; j >>= 1) {
            for (int i = tid; i < n; i += nthreads) {
                int ixj = i ^ j;
                if (ixj > i) {
                    u64 a = s[i], c = s[ixj];
                    bool up = ((i & k) == 0);
                    if (up ? (a < c) : (a > c)) { s[i] = c; s[ixj] = a; }
                }
            }
            __syncthreads();
        }
    }
}

// ---------------------------------------------------------------------------
// Fused per-(b,c): sort candidates + gather boxes + IoU mask + greedy scan.
// Dyn smem: mask u32[1024*32] (128K) | boxes 5*1024 f32 (20K) | keys u64[2048] (16K)
#define K2AB_SMEM (131072 + 20480 + 16384)

__global__ void __launch_bounds__(1024, 1) k2ab(const float* __restrict__ boxes) {
    extern __shared__ unsigned char smem[];
    u32*   sm   = reinterpret_cast<u32*>(smem);
    float* sx1  = reinterpret_cast<float*>(smem + 131072);
    float* sy1  = sx1 + KP;
    float* sx2  = sy1 + KP;
    float* sy2  = sx2 + KP;
    float* sar  = sy2 + KP;
    u64*   keys = reinterpret_cast<u64*>(smem + 131072 + 20480);

    int bc  = blockIdx.x;
    int b   = bc >> 3;
    int c   = bc & 7;
    int tid = threadIdx.x;

    int cnt = g_cnt[bc];
    if (cnt > CAP) cnt = CAP;
    int P = 64;
    while (P < cnt) P <<= 1;

    // zero mask region + load candidate keys
    {
        uint4 z = make_uint4(0,0,0,0);
        uint4* m4 = reinterpret_cast<uint4*>(sm);
        for (int t = tid; t < 8192; t += 1024) m4[t] = z;
        for (int t = tid; t < P; t += 1024) {
            u64 k = 0ull;
            if (t < cnt) {
                u32 sb = __float_as_uint(g_cscore[bc * CAP + t]);
                u32 iv = ~(u32)g_cidx[bc * CAP + t];
                k = ((u64)sb << 32) | (u64)iv;
            }
            keys[t] = k;
        }
    }
    __syncthreads();
    bitonic_desc(keys, P, tid, 1024);

    int M = cnt < KP ? cnt : KP;
    int nW = (M + 31) >> 5;
    int nG = (nW + 3) >> 2;

    // gather sorted candidate boxes into smem
    if (tid < M) {
        int idx = (int)(~(u32)keys[tid]);
        float4 bp = reinterpret_cast<const float4*>(boxes)[(size_t)(b * NN + idx)];
        sx1[tid] = bp.x; sy1[tid] = bp.y; sx2[tid] = bp.z; sy2[tid] = bp.w;
        sar[tid] = __fmul_rn(__fsub_rn(bp.z, bp.x), __fsub_rn(bp.w, bp.y));
    }
    __syncthreads();

    int w = tid >> 5, lane = tid & 31;
    // mask build: item = (iw, g-chunk of 4 words), round-robin over 32 warps
    int e = 0;
    for (int iw = 0; iw < nW; iw++) {
        for (int g = iw >> 2; g < nG; g++, e++) {
            if ((e & 31) != w) continue;
            float jx1[4], jy1[4], jx2[4], jy2[4], ja[4];
            int jbase = (g << 7) + lane;
#pragma unroll
            for (int k = 0; k < 4; k++) {
                int j = jbase + (k << 5);
                jx1[k] = sx1[j]; jy1[k] = sy1[j];
                jx2[k] = sx2[j]; jy2[k] = sy2[j];
                ja[k]  = sar[j];
            }
            int i0 = iw << 5;
            int dmax = M - i0; if (dmax > 32) dmax = 32;
            for (int d = 0; d < dmax; d++) {
                int i = i0 + d;
                float ix1 = sx1[i], iy1 = sy1[i], ix2 = sx2[i], iy2 = sy2[i], ia = sar[i];
                u32 mm[4];
#pragma unroll
                for (int k = 0; k < 4; k++) {
                    int j = jbase + (k << 5);
                    float ww = fmaxf(__fsub_rn(fminf(ix2, jx2[k]), fmaxf(ix1, jx1[k])), 0.0f);
                    float hh = fmaxf(__fsub_rn(fminf(iy2, jy2[k]), fmaxf(iy1, jy1[k])), 0.0f);
                    float inter = __fmul_rn(ww, hh);
                    float den   = __fsub_rn(__fadd_rn(ia, ja[k]), inter);
                    bool p = (j > i) && (j < M) && (__fdiv_rn(inter, den) > 0.5f);
                    mm[k] = __ballot_sync(0xffffffffu, p);
                }
                if (lane == 0)
                    reinterpret_cast<uint4*>(sm)[(i << 3) + g] = make_uint4(mm[0], mm[1], mm[2], mm[3]);
            }
        }
    }
    __syncthreads();

    // serial greedy scan by warp 0: branch-free 8-cyc chain per element.
    if (w == 0) {
        u32 RW[8], DG[8];
#pragma unroll
        for (int d = 0; d < 8; d++) {
            RW[d] = sm[(d << 5) + lane];
            DG[d] = sm[(d << 5) + (d >> 5)];
        }
        u32 remv = 0u, keepreg = 0u;
        for (int g1 = 0; g1 < nW; g1++) {
            u32 cur = __shfl_sync(0xffffffffu, remv, g1);
            u32 kw = 0u;
#pragma unroll
            for (int d = 0; d < 32; d++) {
                int i = (g1 << 5) + d;
                u32 rw = RW[i & 7], dg = DG[i & 7];
                int ip = i + 8; if (ip > 1023) ip = 1023;
                RW[i & 7] = sm[(ip << 5) + lane];
                DG[i & 7] = sm[(ip << 5) + (ip >> 5)];
                u32 smask = (u32)((int)(cur << (31 - d)) >> 31);  // all-ones if suppressed
                kw   |= ~smask & (1u << d);
                cur  |= dg & ~smask;
                remv |= rw & ~smask;
            }
            if (lane == g1) keepreg = kw;
        }
        // mask tail bits beyond M
        {
            int lastg = (M - 1) >> 5;
            u32 tail = (M & 31) ? ((1u << (M & 31)) - 1u) : 0xffffffffu;
            if (M == 0) keepreg = 0u;
            else if (lane == lastg) keepreg &= tail;
            if (lane > lastg) keepreg = 0u;
        }

        // compact kept entries (order preserved -> still score-sorted), cap 128
        int cntl = __popc(keepreg);
        int pre = cntl;
#pragma unroll
        for (int o = 1; o < 32; o <<= 1) {
            int vv = __shfl_up_sync(0xffffffffu, pre, o);
            if (lane >= o) pre += vv;
        }
        int off = pre - cntl;
        int total = __shfl_sync(0xffffffffu, pre, 31);
        if (lane == 0) g_kcnt[bc] = total < 128 ? total : 128;
        u32 wb = keepreg;
        while (wb && off < 128) {
            int b2 = __ffs(wb) - 1;
            wb &= wb - 1;
            int i = (lane << 5) + b2;
            u64 sk = keys[i];
            g_ckey[bc * 128 + off]    = (sk & 0xffffffff00000000ull) | (u64)(~(u32)(c * KP + i));
            g_cidxsel[bc * 128 + off] = (int)(~(u32)sk);
            off++;
        }
    }
}

// ---------------------------------------------------------------------------
// Final top-100 by parallel rank-selection over 8 sorted lists of <=128.
__global__ void __launch_bounds__(1024) k3_rank(const float* __restrict__ boxes,
                                                const float* __restrict__ rot,
                                                const float* __restrict__ trans,
                                                float* __restrict__ out) {
    __shared__ u64 lists[8][128];
    __shared__ int written[MAXD];
    int b = blockIdx.x, tid = threadIdx.x;
    int c = tid >> 7, k = tid & 127;
    int bc = b * 8 + c;

    if (tid < 8)    g_cnt[b * 8 + tid] = 0;   // reset for next graph replay
    if (tid < MAXD) written[tid] = 0;

    u64 key = 0ull;
    if (k < g_kcnt[bc]) key = g_ckey[bc * 128 + k];
    lists[c][k] = key;
    __syncthreads();

    float* ob   = out;
    float* os   = out + 3200;
    float* ol   = out + 4000;
    float* orot = out + 4800;
    float* otr  = out + 7200;

    if (key != 0ull) {
        int rank = 0;
#pragma unroll
        for (int c2 = 0; c2 < 8; c2++) {
            const u64* L = lists[c2];
            int lo = 0, hi = 128;
#pragma unroll
            for (int s = 0; s < 8; s++) {
                if (lo < hi) {
                    int mid = (lo + hi) >> 1;
                    if (L[mid] > key) lo = mid + 1; else hi = mid;
                }
            }
            rank += lo;   // count of entries strictly greater than key
        }
        if (rank < MAXD) {
            written[rank] = 1;
            int base = b * MAXD + rank;
            int idx  = g_cidxsel[bc * 128 + k];
            float s  = __uint_as_float((u32)(key >> 32));
            size_t g = (size_t)(b * NN + idx);
            float4 bp = reinterpret_cast<const float4*>(boxes)[g];
            ob[base * 4 + 0] = bp.x;
            ob[base * 4 + 1] = bp.y;
            ob[base * 4 + 2] = bp.z;
            ob[base * 4 + 3] = bp.w;
            os[base] = s;
            ol[base] = (float)c;
            const float* rp = rot + g * 3;
            orot[base * 3 + 0] = rp[0];
            orot[base * 3 + 1] = rp[1];
            orot[base * 3 + 2] = rp[2];
            const float* tp = trans + g * 3;
            otr[base * 3 + 0] = tp[0];
            otr[base * 3 + 1] = tp[1];
            otr[base * 3 + 2] = tp[2];
        }
    }
    __syncthreads();
    if (tid < MAXD && !written[tid]) {
        int base = b * MAXD + tid;
        ob[base * 4 + 0] = -1.0f;
        ob[base * 4 + 1] = -1.0f;
        ob[base * 4 + 2] = -1.0f;
        ob[base * 4 + 3] = -1.0f;
        os[base] = -1.0f;
        ol[base] = -1.0f;
        orot[base * 3 + 0] = -1.0f;
        orot[base * 3 + 1] = -1.0f;
        orot[base * 3 + 2] = -1.0f;
        otr[base * 3 + 0] = -1.0f;
        otr[base * 3 + 1] = -1.0f;
        otr[base * 3 + 2] = -1.0f;
    }
}

// ---------------------------------------------------------------------------
extern "C" void kernel_launch(void* const* d_in, const int* in_sizes, int n_in,
                              void* d_out, int out_size) {
    const float* boxes = (const float*)d_in[0];
    const float* cls   = (const float*)d_in[1];
    const float* rot   = (const float*)d_in[2];
    const float* trans = (const float*)d_in[3];
    float* out = (float*)d_out;

    cudaFuncSetAttribute(k2ab, cudaFuncAttributeMaxDynamicSharedMemorySize, K2AB_SMEM);

    k1_cand<<<dim3((NN + 255) / 256, BB), 256>>>(cls);
    k2ab<<<BB * CC, 1024, K2AB_SMEM>>>(boxes);
    k3_rank<<<BB, 1024>>>(boxes, rot, trans, out);
}

// round 10
// speedup vs baseline: 1.6144x; 1.4955x over previous
#include <cuda_runtime.h>
#include <cuda_bf16.h>
#include <cstdint>

#define BB 8
#define NN 50000
#define CC 8
#define CAP 2048
#define KP 1024
#define MAXD 100
#define SCORE_THR 0.99f

typedef unsigned long long u64;
typedef unsigned int u32;

// ---------------- device scratch (no allocations allowed) -------------------
__device__ int   g_cnt[BB * CC];          // zero at load; re-zeroed by k3_rank
__device__ float g_cscore[BB * CC * CAP];
__device__ int   g_cidx[BB * CC * CAP];

__device__ int   g_M[BB * CC];
__device__ float g_sx1[BB * CC * KP];     // .bss zero: rows >= M stay 0 forever
__device__ float g_sy1[BB * CC * KP];
__device__ float g_sx2[BB * CC * KP];
__device__ float g_sy2[BB * CC * KP];
__device__ float g_sar[BB * CC * KP];
__device__ u64   g_skey[BB * CC * KP];
__device__ int   g_sidx[BB * CC * KP];

__device__ u32   g_mask[BB * CC * KP * 32];  // 8 MB; unwritten words stay 0

__device__ int   g_kcnt[BB * CC];
__device__ u64   g_ckey[BB * CC * 128];
__device__ int   g_cidxsel[BB * CC * 128];

// ---------------------------------------------------------------------------
// Candidate compaction: 2 points/thread, one batched atomic warp-instr.
__global__ void __launch_bounds__(256) k1_cand(const float* __restrict__ cls) {
    int b  = blockIdx.y;
    int t  = threadIdx.x;
    int n0 = blockIdx.x * 512 + t;       // always < NN for grid.x = 98
    int n1 = n0 + 256;
    bool ok1 = n1 < NN;

    float a[8], dd[8];
    {
        const float4* p = reinterpret_cast<const float4*>(cls + ((size_t)b * NN + n0) * CC);
        float4 x = p[0], y = p[1];
        a[0]=x.x; a[1]=x.y; a[2]=x.z; a[3]=x.w;
        a[4]=y.x; a[5]=y.y; a[6]=y.z; a[7]=y.w;
    }
    if (ok1) {
        const float4* p = reinterpret_cast<const float4*>(cls + ((size_t)b * NN + n1) * CC);
        float4 x = p[0], y = p[1];
        dd[0]=x.x; dd[1]=x.y; dd[2]=x.z; dd[3]=x.w;
        dd[4]=y.x; dd[5]=y.y; dd[6]=y.z; dd[7]=y.w;
    } else {
#pragma unroll
        for (int c = 0; c < 8; c++) dd[c] = 0.0f;
    }

    int lane = t & 31;
    u32 m0[8], m1[8];
    u32 myc0 = 0, myc1 = 0;
#pragma unroll
    for (int c = 0; c < 8; c++) {
        m0[c] = __ballot_sync(0xffffffffu, a[c]  > SCORE_THR);
        m1[c] = __ballot_sync(0xffffffffu, dd[c] > SCORE_THR);
        if (lane == c) { myc0 = m0[c]; myc1 = m1[c]; }
    }
    int tot = __popc(myc0) + __popc(myc1);
    int base = 0;
    if (lane < 8 && tot > 0) base = atomicAdd(&g_cnt[b * 8 + lane], tot);
    u32 lt = (1u << lane) - 1u;
#pragma unroll
    for (int c = 0; c < 8; c++) {
        int basec = __shfl_sync(0xffffffffu, base, c);
        int bcC = (b * 8 + c) * CAP;
        if (a[c] > SCORE_THR) {
            int off = basec + __popc(m0[c] & lt);
            if (off < CAP) { g_cscore[bcC + off] = a[c]; g_cidx[bcC + off] = n0; }
        }
        if (dd[c] > SCORE_THR) {
            int off = basec + __popc(m0[c]) + __popc(m1[c] & lt);
            if (off < CAP) { g_cscore[bcC + off] = dd[c]; g_cidx[bcC + off] = n1; }
        }
    }
}

// ---------------------------------------------------------------------------
__device__ __forceinline__ void bitonic_desc(u64* s, int n, int tid, int nthreads) {
    for (int k = 2; k <= n; k <<= 1) {
        for (int j = k >> 1; j > 0; j >>= 1) {
            for (int i = tid; i < n; i += nthreads) {
                int ixj = i ^ j;
                if (ixj > i) {
                    u64 a = s[i], c = s[ixj];
                    bool up = ((i & k) == 0);
                    if (up ? (a < c) : (a > c)) { s[i] = c; s[ixj] = a; }
                }
            }
            __syncthreads();
        }
    }
}

// ---------------------------------------------------------------------------
// Sort candidates (size = next pow2 of cnt) + write sorted box data.
__global__ void __launch_bounds__(512) k2a_sort(const float* __restrict__ boxes) {
    __shared__ u64 keys[CAP];
    int bc = blockIdx.x;
    int b  = bc >> 3;
    int tid = threadIdx.x;

    int cnt = g_cnt[bc];
    if (cnt > CAP) cnt = CAP;
    int P = 64;
    while (P < cnt) P <<= 1;

    for (int t = tid; t < P; t += 512) {
        u64 k = 0ull;
        if (t < cnt) {
            u32 sb = __float_as_uint(g_cscore[bc * CAP + t]);
            u32 iv = ~(u32)g_cidx[bc * CAP + t];
            k = ((u64)sb << 32) | (u64)iv;
        }
        keys[t] = k;
    }
    __syncthreads();
    bitonic_desc(keys, P, tid, 512);

    int M = cnt < KP ? cnt : KP;
    if (tid == 0) g_M[bc] = M;

    for (int t = tid; t < M; t += 512) {
        u64 kk = keys[t];
        int idx = (int)(~(u32)kk);
        float4 bp = reinterpret_cast<const float4*>(boxes)[(size_t)(b * NN + idx)];
        int o = bc * KP + t;
        g_sx1[o] = bp.x; g_sy1[o] = bp.y; g_sx2[o] = bp.z; g_sy2[o] = bp.w;
        g_sar[o] = __fmul_rn(__fsub_rn(bp.z, bp.x), __fsub_rn(bp.w, bp.y));
        g_skey[o] = kk;
        g_sidx[o] = idx;
    }
}

// ---------------------------------------------------------------------------
// Triangular IoU mask build, item = (iw, jw) 32x32 tile, 128 slots per bc.
// Division-free exact test: rn(inter/den) > 0.5  <=>  inter - 0.5*den > (0.5*den)*2^-24
#define NSPLIT 16

__global__ void __launch_bounds__(256) k2b_mask() {
    __shared__ float sx1[KP], sy1[KP], sx2[KP], sy2[KP], sar[KP];
    int bc = blockIdx.x >> 4;
    int s  = blockIdx.x & 15;
    int M  = g_M[bc];
    int nW = (M + 31) >> 5;

    for (int t = threadIdx.x; t < KP; t += 256) {
        int o = bc * KP + t;        // rows >= M are zero in global (.bss, never written)
        sx1[t] = g_sx1[o]; sy1[t] = g_sy1[o];
        sx2[t] = g_sx2[o]; sy2[t] = g_sy2[o];
        sar[t] = g_sar[o];
    }
    __syncthreads();

    int w = threadIdx.x >> 5, lane = threadIdx.x & 31;
    int slot = s * 8 + w;            // 0..127
    int e = 0;
    for (int iw = 0; iw < nW; iw++) {
        for (int jw = iw; jw < nW; jw++, e++) {
            if ((e & 127) != slot) continue;
            int j = (jw << 5) + lane;
            float jx1 = sx1[j], jy1 = sy1[j], jx2 = sx2[j], jy2 = sy2[j], ja = sar[j];
            int i0 = iw << 5;
            int dmax = M - i0; if (dmax > 32) dmax = 32;
            for (int d = 0; d < dmax; d++) {
                int i = i0 + d;
                float ix1 = sx1[i], iy1 = sy1[i], ix2 = sx2[i], iy2 = sy2[i], ia = sar[i];
                float ww = fmaxf(__fsub_rn(fminf(ix2, jx2), fmaxf(ix1, jx1)), 0.0f);
                float hh = fmaxf(__fsub_rn(fminf(iy2, jy2), fmaxf(iy1, jy1)), 0.0f);
                float inter = __fmul_rn(ww, hh);
                float den   = __fsub_rn(__fadd_rn(ia, ja), inter);
                float th    = __fmul_rn(0.5f, den);          // exact
                float diff  = __fsub_rn(inter, th);          // exact (Sterbenz)
                float eps   = __fmul_rn(th, 5.9604645e-8f);  // t * 2^-24, exact
                bool p = (j > i) && (j < M) && (diff > eps);
                u32 mm = __ballot_sync(0xffffffffu, p);
                if (lane == 0) g_mask[((size_t)bc << 15) + (i << 5) + jw] = mm;
            }
        }
    }
}

// ---------------------------------------------------------------------------
// Serial greedy scan: one warp per (b,c), guard-free 32-deep prefetch ring,
// branch-free 8-cyc chain per element. Then compaction of kept entries.
__global__ void __launch_bounds__(32) k2c_scan() {
    int bc   = blockIdx.x;
    int lane = threadIdx.x;
    int c    = bc & 7;
    int M    = g_M[bc];
    if (M == 0) { if (lane == 0) g_kcnt[bc] = 0; return; }
    int nW = (M + 31) >> 5;

    const u32* mrow = g_mask + ((size_t)bc << 15);

    u32 RW[32], DG[32];
#pragma unroll
    for (int d = 0; d < 32; d++) {
        RW[d] = mrow[(d << 5) + lane];
        DG[d] = mrow[(d << 5) + (d >> 5)];
    }
    u32 remv = 0u, keepreg = 0u;
    for (int g1 = 0; g1 < nW; g1++) {
        u32 cur = __shfl_sync(0xffffffffu, remv, g1);
        u32 kw = 0u;
#pragma unroll
        for (int d = 0; d < 32; d++) {
            int i = (g1 << 5) + d;
            u32 rw = RW[d], dg = DG[d];
            int ip = i + 32; if (ip > 1023) ip = 1023;
            RW[d] = mrow[(ip << 5) + lane];
            DG[d] = mrow[(ip << 5) + (ip >> 5)];
            u32 smask = (u32)((int)(cur << (31 - d)) >> 31);  // all-ones if suppressed
            kw   |= ~smask & (1u << d);
            cur  |= dg & ~smask;
            remv |= rw & ~smask;
        }
        if (lane == g1) keepreg = kw;
    }
    // mask tail bits beyond M
    {
        int lastg = (M - 1) >> 5;
        u32 tail = (M & 31) ? ((1u << (M & 31)) - 1u) : 0xffffffffu;
        if (lane == lastg) keepreg &= tail;
        if (lane > lastg)  keepreg = 0u;
    }

    // compact kept entries (order preserved -> score-sorted), cap 128
    int cntl = __popc(keepreg);
    int pre = cntl;
#pragma unroll
    for (int o = 1; o < 32; o <<= 1) {
        int vv = __shfl_up_sync(0xffffffffu, pre, o);
        if (lane >= o) pre += vv;
    }
    int off = pre - cntl;
    int total = __shfl_sync(0xffffffffu, pre, 31);
    if (lane == 0) g_kcnt[bc] = total < 128 ? total : 128;
    u32 wb = keepreg;
    while (wb && off < 128) {
        int b2 = __ffs(wb) - 1;
        wb &= wb - 1;
        int i = (lane << 5) + b2;
        u64 sk = g_skey[bc * KP + i];
        g_ckey[bc * 128 + off]    = (sk & 0xffffffff00000000ull) | (u64)(~(u32)(c * KP + i));
        g_cidxsel[bc * 128 + off] = g_sidx[bc * KP + i];
        off++;
    }
}

// ---------------------------------------------------------------------------
// Final top-100 by parallel rank-selection over 8 sorted lists of <=128.
__global__ void __launch_bounds__(1024) k3_rank(const float* __restrict__ boxes,
                                                const float* __restrict__ rot,
                                                const float* __restrict__ trans,
                                                float* __restrict__ out) {
    __shared__ u64 lists[8][128];
    __shared__ int written[MAXD];
    int b = blockIdx.x, tid = threadIdx.x;
    int c = tid >> 7, k = tid & 127;
    int bc = b * 8 + c;

    if (tid < 8)    g_cnt[b * 8 + tid] = 0;   // reset for next graph replay
    if (tid < MAXD) written[tid] = 0;

    u64 key = 0ull;
    if (k < g_kcnt[bc]) key = g_ckey[bc * 128 + k];
    lists[c][k] = key;
    __syncthreads();

    float* ob   = out;
    float* os   = out + 3200;
    float* ol   = out + 4000;
    float* orot = out + 4800;
    float* otr  = out + 7200;

    if (key != 0ull) {
        int rank = 0;
#pragma unroll
        for (int c2 = 0; c2 < 8; c2++) {
            const u64* L = lists[c2];
            int lo = 0, hi = 128;
#pragma unroll
            for (int s = 0; s < 8; s++) {
                if (lo < hi) {
                    int mid = (lo + hi) >> 1;
                    if (L[mid] > key) lo = mid + 1; else hi = mid;
                }
            }
            rank += lo;   // count of entries strictly greater than key
        }
        if (rank < MAXD) {
            written[rank] = 1;
            int base = b * MAXD + rank;
            int idx  = g_cidxsel[bc * 128 + k];
            float s  = __uint_as_float((u32)(key >> 32));
            size_t g = (size_t)(b * NN + idx);
            float4 bp = reinterpret_cast<const float4*>(boxes)[g];
            ob[base * 4 + 0] = bp.x;
            ob[base * 4 + 1] = bp.y;
            ob[base * 4 + 2] = bp.z;
            ob[base * 4 + 3] = bp.w;
            os[base] = s;
            ol[base] = (float)c;
            const float* rp = rot + g * 3;
            orot[base * 3 + 0] = rp[0];
            orot[base * 3 + 1] = rp[1];
            orot[base * 3 + 2] = rp[2];
            const float* tp = trans + g * 3;
            otr[base * 3 + 0] = tp[0];
            otr[base * 3 + 1] = tp[1];
            otr[base * 3 + 2] = tp[2];
        }
    }
    __syncthreads();
    if (tid < MAXD && !written[tid]) {
        int base = b * MAXD + tid;
        ob[base * 4 + 0] = -1.0f;
        ob[base * 4 + 1] = -1.0f;
        ob[base * 4 + 2] = -1.0f;
        ob[base * 4 + 3] = -1.0f;
        os[base] = -1.0f;
        ol[base] = -1.0f;
        orot[base * 3 + 0] = -1.0f;
        orot[base * 3 + 1] = -1.0f;
        orot[base * 3 + 2] = -1.0f;
        otr[base * 3 + 0] = -1.0f;
        otr[base * 3 + 1] = -1.0f;
        otr[base * 3 + 2] = -1.0f;
    }
}

// ---------------------------------------------------------------------------
extern "C" void kernel_launch(void* const* d_in, const int* in_sizes, int n_in,
                              void* d_out, int out_size) {
    const float* boxes = (const float*)d_in[0];
    const float* cls   = (const float*)d_in[1];
    const float* rot   = (const float*)d_in[2];
    const float* trans = (const float*)d_in[3];
    float* out = (float*)d_out;

    k1_cand<<<dim3((NN + 511) / 512, BB), 256>>>(cls);
    k2a_sort<<<BB * CC, 512>>>(boxes);
    k2b_mask<<<BB * CC * NSPLIT, 256>>>();
    k2c_scan<<<BB * CC, 32>>>();
    k3_rank<<<BB, 1024>>>(boxes, rot, trans, out);
}